// round 13
// baseline (speedup 1.0000x reference)
#include <cuda_runtime.h>
#include <cuda_bf16.h>
#include <cuda_fp16.h>
#include <cstdint>

// Problem constants
#define BB 4
#define SS 2048
#define DD 1024
#define HH 16
#define HD 64
#define BS (BB*SS)          // 8192

// ---------------------------------------------------------------------------
// Scratch (device globals; no allocation allowed)
// ---------------------------------------------------------------------------
__device__ __half g_x16[BS*DD];                             // x fp16
__device__ __half g_w16[3*DD*DD];                           // fused Wq|Wk|Wv fp16
__device__ __half g_wo16[DD*DD];                            // Wo fp16
__device__ __half g_c16[BS*DD];                             // ctx fp16

__device__ __half g_q16[BS*DD];                             // Q (scaled) fp16
__device__ __half g_k16[BS*DD];                             // K fp16
__device__ __half g_v16[BS*DD];                             // V fp16

// ---------------------------------------------------------------------------
// Portable (compute_103-safe) PTX helpers
// ---------------------------------------------------------------------------
__device__ __forceinline__ uint32_t smem_u32(const void* p) {
    uint32_t a;
    asm("{ .reg .u64 t; cvta.to.shared.u64 t, %1; cvt.u32.u64 %0, t; }" : "=r"(a) : "l"(p));
    return a;
}
__device__ __forceinline__ void cp16(uint32_t dst, const void* src) {
    asm volatile("cp.async.cg.shared.global [%0], [%1], 16;" :: "r"(dst), "l"(src) : "memory");
}
#define CP_COMMIT() asm volatile("cp.async.commit_group;" ::: "memory")
#define CP_WAIT0()  asm volatile("cp.async.wait_group 0;" ::: "memory")
#define CP_WAIT1()  asm volatile("cp.async.wait_group 1;" ::: "memory")
#define CP_WAIT2()  asm volatile("cp.async.wait_group 2;" ::: "memory")

__device__ __forceinline__ void ldsm4(uint32_t& r0, uint32_t& r1, uint32_t& r2, uint32_t& r3,
                                      uint32_t addr) {
    asm volatile("ldmatrix.sync.aligned.m8n8.x4.shared.b16 {%0,%1,%2,%3}, [%4];"
                 : "=r"(r0), "=r"(r1), "=r"(r2), "=r"(r3) : "r"(addr));
}
__device__ __forceinline__ void ldsm4t(uint32_t& r0, uint32_t& r1, uint32_t& r2, uint32_t& r3,
                                       uint32_t addr) {
    asm volatile("ldmatrix.sync.aligned.m8n8.x4.trans.shared.b16 {%0,%1,%2,%3}, [%4];"
                 : "=r"(r0), "=r"(r1), "=r"(r2), "=r"(r3) : "r"(addr));
}
// fp16 mma
__device__ __forceinline__ void mma16816h(float* c,
                                          uint32_t a0, uint32_t a1, uint32_t a2, uint32_t a3,
                                          uint32_t b0, uint32_t b1) {
    asm volatile("mma.sync.aligned.m16n8k16.row.col.f32.f16.f16.f32 "
                 "{%0,%1,%2,%3}, {%4,%5,%6,%7}, {%8,%9}, {%0,%1,%2,%3};"
                 : "+f"(c[0]), "+f"(c[1]), "+f"(c[2]), "+f"(c[3])
                 : "r"(a0), "r"(a1), "r"(a2), "r"(a3), "r"(b0), "r"(b1));
}
__device__ __forceinline__ float ex2f(float x) {
    float y; asm("ex2.approx.f32 %0, %1;" : "=f"(y) : "f"(x)); return y;
}
__device__ __forceinline__ uint32_t packh(float x, float y) {
    __half2 t = __floats2half2_rn(x, y);
    return *(uint32_t*)&t;
}

// ---------------------------------------------------------------------------
// Fused fp32 -> fp16 convert (2 independent chunks per thread for MLP)
// ---------------------------------------------------------------------------
#define XN4 (BS*DD/4)      // 2097152
#define WN4 (DD*DD/4)      // 262144
#define CVT_TOTAL (XN4 + 4*WN4)
#define CVT_HALF  (CVT_TOTAL / 2)

__device__ __forceinline__ void cvt_one(int i,
                                        const float* __restrict__ x,
                                        const float* __restrict__ wq,
                                        const float* __restrict__ wk,
                                        const float* __restrict__ wv,
                                        const float* __restrict__ wo)
{
    const float* src;
    __half* dst;
    int off;
    if (i < XN4)                { src = x;  dst = g_x16;            off = i; }
    else if (i < XN4 + WN4)     { src = wq; dst = g_w16;            off = i - XN4; }
    else if (i < XN4 + 2*WN4)   { src = wk; dst = g_w16 + DD*DD;    off = i - XN4 - WN4; }
    else if (i < XN4 + 3*WN4)   { src = wv; dst = g_w16 + 2*DD*DD;  off = i - XN4 - 2*WN4; }
    else                        { src = wo; dst = g_wo16;           off = i - XN4 - 3*WN4; }
    float4 v = ((const float4*)src)[off];
    ((uint32_t*)dst)[off*2+0] = packh(v.x, v.y);
    ((uint32_t*)dst)[off*2+1] = packh(v.z, v.w);
}

__global__ __launch_bounds__(256)
void cvt_all_kernel(const float* __restrict__ x,
                    const float* __restrict__ wq, const float* __restrict__ wk,
                    const float* __restrict__ wv, const float* __restrict__ wo)
{
    int i = blockIdx.x * 256 + threadIdx.x;
    if (i >= CVT_HALF) return;
    cvt_one(i, x, wq, wk, wv, wo);
    cvt_one(i + CVT_HALF, x, wq, wk, wv, wo);
}

// ---------------------------------------------------------------------------
// fp16 single-pass GEMM via mma.sync: C = A * B^T.  (round-11/12 proven)
// CTA 128x128, BK=64, 3-stage cp.async, 8 warps (2M x 4N), warp 64x32.
// 2 CTAs per SM; 16 k-chunks.
// ---------------------------------------------------------------------------
#define GM_BM 128
#define GM_BN 128
#define GM_BK 64
#define GM_TILES 16            // K=1024 / 64
#define LSTR 72                // smem row stride in halves (144B), conflict-free
#define GM_THREADS 256

#define TEN_A  18432u          // 128x64 fp16 tensor (LSTR-padded)
#define STG_B  36864u          // A + B per stage
#define GSMEM  110592          // 3 stages (2 CTAs/SM -> 221KB <= 228KB)

#define QSCALE 0.18033688011112042f   // (1/8) * log2(e)

__global__ __launch_bounds__(GM_THREADS, 2)
void gemm_fp16_kernel(const __half* __restrict__ Aa,
                      const __half* __restrict__ Bw,
                      float* __restrict__ outp,
                      const float* __restrict__ bias,
                      int mode)
{
    extern __shared__ char smem[];
    const uint32_t sb = smem_u32(smem);

    const int tid = threadIdx.x;
    const int lid = tid & 31;
    const int wid = tid >> 5;     // 0..7
    const int wm = wid >> 2;      // 0..1 (64 rows)
    const int wn = wid & 3;       // 0..3 (32 cols)

    const int m0 = blockIdx.x * GM_BM;
    const int n0 = blockIdx.y * GM_BN;

    float acc[4][4][4];
    #pragma unroll
    for (int i = 0; i < 4; i++)
        #pragma unroll
        for (int j = 0; j < 4; j++)
            #pragma unroll
            for (int c = 0; c < 4; c++) acc[i][j][c] = 0.f;

    auto load_tile = [&](int t) {
        const int k0 = t * GM_BK;
        const int st = t % 3;
        const uint32_t base = sb + (uint32_t)st * STG_B;
        #pragma unroll
        for (int it = 0; it < 4; it++) {
            int idx = tid + it * GM_THREADS;
            int r = idx >> 3, c = idx & 7;
            cp16(base + (uint32_t)(r * LSTR + c * 8) * 2,
                 Aa + (size_t)(m0 + r) * DD + k0 + c * 8);
        }
        #pragma unroll
        for (int it = 0; it < 4; it++) {
            int idx = tid + it * GM_THREADS;
            int r = idx >> 3, c = idx & 7;
            cp16(base + TEN_A + (uint32_t)(r * LSTR + c * 8) * 2,
                 Bw + (size_t)(n0 + r) * DD + k0 + c * 8);
        }
        CP_COMMIT();
    };

    load_tile(0);
    load_tile(1);

    const int q = lid >> 3;
    const int r = lid & 7;
    const int arow = r + (q & 1) * 8;
    const int acol = (q >> 1) * 8;
    const int brow = r + (q >> 1) * 8;
    const int bcol = (q & 1) * 8;

    for (int i = 0; i < GM_TILES; i++) {
        if (i + 1 < GM_TILES) { CP_WAIT1(); } else { CP_WAIT0(); }
        __syncthreads();
        if (i + 2 < GM_TILES) load_tile(i + 2);

        const uint32_t stg = sb + (uint32_t)(i % 3) * STG_B;

        #pragma unroll
        for (int kst = 0; kst < 4; kst++) {
            const int kb = kst * 16;
            uint32_t b[4][2];
            #pragma unroll
            for (int np = 0; np < 2; np++) {
                uint32_t addr = stg + TEN_A +
                    (uint32_t)((wn * 32 + np * 16 + brow) * LSTR + kb + bcol) * 2;
                ldsm4(b[2*np][0], b[2*np][1], b[2*np+1][0], b[2*np+1][1], addr);
            }
            uint32_t a[4][4];
            #pragma unroll
            for (int mt = 0; mt < 4; mt++) {
                uint32_t addr = stg +
                    (uint32_t)((wm * 64 + mt * 16 + arow) * LSTR + kb + acol) * 2;
                ldsm4(a[mt][0], a[mt][1], a[mt][2], a[mt][3], addr);
            }
            #pragma unroll
            for (int mt = 0; mt < 4; mt++)
                #pragma unroll
                for (int nt = 0; nt < 4; nt++)
                    mma16816h(acc[mt][nt], a[mt][0], a[mt][1], a[mt][2], a[mt][3],
                              b[nt][0], b[nt][1]);
        }
    }

    // Epilogue
    if (mode == 0) {
        const int sel = n0 >> 10;
        __half* __restrict__ op = (sel == 0) ? g_q16 : (sel == 1) ? g_k16 : g_v16;
        const float scale = (sel == 0) ? QSCALE : 1.0f;
        const int ncta = n0 & (DD - 1);
        #pragma unroll
        for (int mt = 0; mt < 4; mt++) {
            int row = m0 + wm * 64 + mt * 16 + (lid >> 2);
            #pragma unroll
            for (int nt = 0; nt < 4; nt++) {
                int col = ncta + wn * 32 + nt * 8 + (lid & 3) * 2;
                *(uint32_t*)&op[(size_t)row * DD + col] =
                    packh(acc[mt][nt][0] * scale, acc[mt][nt][1] * scale);
                *(uint32_t*)&op[(size_t)(row + 8) * DD + col] =
                    packh(acc[mt][nt][2] * scale, acc[mt][nt][3] * scale);
            }
        }
    } else {
        #pragma unroll
        for (int mt = 0; mt < 4; mt++) {
            int row = m0 + wm * 64 + mt * 16 + (lid >> 2);
            #pragma unroll
            for (int nt = 0; nt < 4; nt++) {
                int col = n0 + wn * 32 + nt * 8 + (lid & 3) * 2;
                float2 bb = *(const float2*)&bias[col];
                float2 v0 = {acc[mt][nt][0] + bb.x, acc[mt][nt][1] + bb.y};
                float2 v1 = {acc[mt][nt][2] + bb.x, acc[mt][nt][3] + bb.y};
                *(float2*)&outp[(size_t)row * DD + col] = v0;
                *(float2*)&outp[(size_t)(row + 8) * DD + col] = v1;
            }
        }
    }
}

// ---------------------------------------------------------------------------
// Flash attention (causal), fp16 MMA, all single-pass.
// S = Q K^T, O = P V. 3-stage KV ring -> ONE __syncthreads per k-tile.
// Safety: at iter kt, loads for kt+2 write stage (kt+2)%3 == (kt-1)%3, which
// every warp finished consuming before passing this iteration's barrier.
// ---------------------------------------------------------------------------
#define BR 128
#define BC 64
#define KSTR 72                 // padded fp16 stride (144B rows)

#define FQ_OFF  0u              // Q: 128*72*2 = 18432
#define FST_OFF 18432u          // 3 stages of 18432
#define FSTAGE  18432u          // per stage: K +0, V +9216
#define FTEN    9216u
#define FSMEM   73728

__global__ __launch_bounds__(256)
void flash_mma_kernel()
{
    extern __shared__ char smem[];
    const uint32_t sb = smem_u32(smem);

    const int tid = threadIdx.x;
    const int lid = tid & 31;
    const int wid = tid >> 5;
    const int itile = blockIdx.x;
    const int bh = blockIdx.y;
    const int b = bh >> 4, h = bh & 15;
    const int qbase = itile * BR;
    const int nkt = 2 * itile + 2;

    const size_t gq  = ((size_t)(b * SS + qbase)) * DD + h * HD;
    const size_t gkv = ((size_t)(b * SS)) * DD + h * HD;

    // Q -> smem
    #pragma unroll
    for (int t = 0; t < 4; t++) {
        int idx = tid + t * 256;            // 0..1023
        int r = idx >> 3;
        int c = idx & 7;
        cp16(sb + FQ_OFF + (uint32_t)(r * KSTR + c * 8) * 2,
             g_q16 + gq + (size_t)r * DD + c * 8);
    }
    CP_COMMIT();

    auto load_kv = [&](int kt) {
        const uint32_t base = sb + FST_OFF + (uint32_t)(kt % 3) * FSTAGE;
        const size_t gk = gkv + (size_t)(kt * BC) * DD;
        #pragma unroll
        for (int t = 0; t < 4; t++) {
            int idx = tid + t * 256;        // 0..1023
            int ten = idx >> 9;             // 0 = K, 1 = V
            int r = (idx >> 3) & 63;
            int c = idx & 7;
            const __half* src = ten ? g_v16 : g_k16;
            cp16(base + (uint32_t)ten * FTEN + (uint32_t)(r * KSTR + c * 8) * 2,
                 src + gk + (size_t)r * DD + c * 8);
        }
        CP_COMMIT();
    };

    load_kv(0);
    if (nkt > 1) load_kv(1);

    CP_WAIT2();                 // Q group done (kv0/kv1 may be pending)
    __syncthreads();

    const int q4 = lid >> 3;
    const int r8 = lid & 7;
    const int arow = r8 + (q4 & 1) * 8;
    const int acol = (q4 >> 1) * 8;
    const int brow = r8 + (q4 >> 1) * 8;
    const int bcol = (q4 & 1) * 8;

    uint32_t qf[4][4];
    #pragma unroll
    for (int ks = 0; ks < 4; ks++) {
        uint32_t ao = (uint32_t)((wid * 16 + arow) * KSTR + ks * 16 + acol) * 2;
        ldsm4(qf[ks][0], qf[ks][1], qf[ks][2], qf[ks][3], sb + FQ_OFF + ao);
    }

    float o[8][4];
    #pragma unroll
    for (int nf = 0; nf < 8; nf++)
        #pragma unroll
        for (int c = 0; c < 4; c++) o[nf][c] = 0.f;
    float m0 = -1e30f, m1 = -1e30f, ls0 = 0.f, ls1 = 0.f;

    const int rowg = qbase + wid * 16 + (lid >> 2);

    for (int kt = 0; kt < nkt; kt++) {
        if (kt + 1 < nkt) { CP_WAIT1(); } else { CP_WAIT0(); }
        __syncthreads();
        if (kt + 2 < nkt) load_kv(kt + 2);

        const uint32_t kb = sb + FST_OFF + (uint32_t)(kt % 3) * FSTAGE;

        // ---- S = Q K^T (single fp16 pass) ----
        float s[8][4];
        #pragma unroll
        for (int nf = 0; nf < 8; nf++)
            #pragma unroll
            for (int c = 0; c < 4; c++) s[nf][c] = 0.f;

        #pragma unroll
        for (int ks = 0; ks < 4; ks++) {
            #pragma unroll
            for (int np = 0; np < 4; np++) {
                uint32_t ao = (uint32_t)((np * 16 + brow) * KSTR + ks * 16 + bcol) * 2;
                uint32_t k0, k1, k2, k3;
                ldsm4(k0, k1, k2, k3, kb + ao);
                mma16816h(s[2*np],   qf[ks][0], qf[ks][1], qf[ks][2], qf[ks][3], k0, k1);
                mma16816h(s[2*np+1], qf[ks][0], qf[ks][1], qf[ks][2], qf[ks][3], k2, k3);
            }
        }

        // ---- causal mask on the last two k-tiles ----
        if (kt >= nkt - 2) {
            const int colb = kt * BC + (lid & 3) * 2;
            #pragma unroll
            for (int nf = 0; nf < 8; nf++) {
                int c0 = colb + nf * 8;
                if (c0     > rowg)     s[nf][0] = -1e30f;
                if (c0 + 1 > rowg)     s[nf][1] = -1e30f;
                if (c0     > rowg + 8) s[nf][2] = -1e30f;
                if (c0 + 1 > rowg + 8) s[nf][3] = -1e30f;
            }
        }

        // ---- online softmax (log2 domain) ----
        float mx0 = -1e30f, mx1 = -1e30f;
        #pragma unroll
        for (int nf = 0; nf < 8; nf++) {
            mx0 = fmaxf(mx0, fmaxf(s[nf][0], s[nf][1]));
            mx1 = fmaxf(mx1, fmaxf(s[nf][2], s[nf][3]));
        }
        mx0 = fmaxf(mx0, __shfl_xor_sync(0xffffffffu, mx0, 1));
        mx0 = fmaxf(mx0, __shfl_xor_sync(0xffffffffu, mx0, 2));
        mx1 = fmaxf(mx1, __shfl_xor_sync(0xffffffffu, mx1, 1));
        mx1 = fmaxf(mx1, __shfl_xor_sync(0xffffffffu, mx1, 2));
        const float nm0 = fmaxf(m0, mx0), nm1 = fmaxf(m1, mx1);
        const float al0 = ex2f(m0 - nm0), al1 = ex2f(m1 - nm1);
        m0 = nm0; m1 = nm1;
        ls0 *= al0; ls1 *= al1;

        #pragma unroll
        for (int nf = 0; nf < 8; nf++) {
            s[nf][0] = ex2f(s[nf][0] - m0);
            s[nf][1] = ex2f(s[nf][1] - m0);
            s[nf][2] = ex2f(s[nf][2] - m1);
            s[nf][3] = ex2f(s[nf][3] - m1);
            ls0 += s[nf][0] + s[nf][1];
            ls1 += s[nf][2] + s[nf][3];
        }
        #pragma unroll
        for (int nf = 0; nf < 8; nf++) {
            o[nf][0] *= al0; o[nf][1] *= al0;
            o[nf][2] *= al1; o[nf][3] *= al1;
        }

        // ---- O += P V (fp16 single pass) ----
        const int vlane_r = lid & 15;
        const int vlane_c = (lid >> 4) * 8;
        #pragma unroll
        for (int ks = 0; ks < 4; ks++) {
            uint32_t pa[4];
            pa[0] = packh(s[2*ks][0],   s[2*ks][1]);
            pa[1] = packh(s[2*ks][2],   s[2*ks][3]);
            pa[2] = packh(s[2*ks+1][0], s[2*ks+1][1]);
            pa[3] = packh(s[2*ks+1][2], s[2*ks+1][3]);
            #pragma unroll
            for (int np = 0; np < 4; np++) {
                uint32_t ao = (uint32_t)((ks * 16 + vlane_r) * KSTR + np * 16 + vlane_c) * 2;
                uint32_t v0, v1, v2, v3;
                ldsm4t(v0, v1, v2, v3, kb + FTEN + ao);
                mma16816h(o[2*np],   pa[0], pa[1], pa[2], pa[3], v0, v1);
                mma16816h(o[2*np+1], pa[0], pa[1], pa[2], pa[3], v2, v3);
            }
        }
        // no trailing barrier: 3-stage ring makes next iteration's loads safe
    }

    // ---- epilogue: normalize, write ctx fp16 ----
    ls0 += __shfl_xor_sync(0xffffffffu, ls0, 1);
    ls0 += __shfl_xor_sync(0xffffffffu, ls0, 2);
    ls1 += __shfl_xor_sync(0xffffffffu, ls1, 1);
    ls1 += __shfl_xor_sync(0xffffffffu, ls1, 2);
    const float li0 = 1.0f / ls0, li1 = 1.0f / ls1;

    const size_t row0 = (size_t)(b * SS + rowg);
    const int colb = h * HD + (lid & 3) * 2;
    #pragma unroll
    for (int nf = 0; nf < 8; nf++) {
        int col = colb + nf * 8;
        *(uint32_t*)&g_c16[row0 * DD + col]       = packh(o[nf][0] * li0, o[nf][1] * li0);
        *(uint32_t*)&g_c16[(row0 + 8) * DD + col] = packh(o[nf][2] * li1, o[nf][3] * li1);
    }
}

// ---------------------------------------------------------------------------

extern "C" void kernel_launch(void* const* d_in, const int* in_sizes, int n_in,
                              void* d_out, int out_size)
{
    const float* x    = (const float*)d_in[0];
    const float* wq   = (const float*)d_in[1];
    const float* wk   = (const float*)d_in[2];
    const float* wv   = (const float*)d_in[3];
    const float* wo   = (const float*)d_in[4];
    const float* wo_b = (const float*)d_in[5];
    float* out = (float*)d_out;

    static int attr_done = 0;
    if (!attr_done) {
        cudaFuncSetAttribute(flash_mma_kernel,
                             cudaFuncAttributeMaxDynamicSharedMemorySize, FSMEM);
        cudaFuncSetAttribute(gemm_fp16_kernel,
                             cudaFuncAttributeMaxDynamicSharedMemorySize, GSMEM);
        attr_done = 1;
    }

    __half *x16, *w16, *wo16, *c16;
    cudaGetSymbolAddress((void**)&x16,  g_x16);
    cudaGetSymbolAddress((void**)&w16,  g_w16);
    cudaGetSymbolAddress((void**)&wo16, g_wo16);
    cudaGetSymbolAddress((void**)&c16,  g_c16);

    // 1. convert x + all weights to fp16 (fused, 2 chunks/thread for MLP)
    cvt_all_kernel<<<(CVT_HALF + 255)/256, 256>>>(x, wq, wk, wv, wo);

    // 2. fused QKV projection (fp16 1-pass, BK=64, 2 CTAs/SM) -> Q/K/V fp16
    gemm_fp16_kernel<<<dim3(BS/GM_BM, 3*DD/GM_BN), GM_THREADS, GSMEM>>>(
        x16, w16, nullptr, nullptr, 0);

    // 3. causal flash attention (fp16, 3-stage single-sync) -> ctx fp16
    flash_mma_kernel<<<dim3(SS/BR, BB*HH), 256, FSMEM>>>();

    // 4. output projection + bias (fp16 1-pass, fp32 out)
    gemm_fp16_kernel<<<dim3(BS/GM_BM, DD/GM_BN), GM_THREADS, GSMEM>>>(
        c16, wo16, out, wo_b, 1);
}

// round 14
// speedup vs baseline: 1.0723x; 1.0723x over previous
#include <cuda_runtime.h>
#include <cuda_bf16.h>
#include <cuda_fp16.h>
#include <cstdint>

// Problem constants
#define BB 4
#define SS 2048
#define DD 1024
#define HH 16
#define HD 64
#define BS (BB*SS)          // 8192

// ---------------------------------------------------------------------------
// Scratch (device globals; no allocation allowed)
// ---------------------------------------------------------------------------
__device__ __half g_x16[BS*DD];                             // x fp16
__device__ __half g_w16[3*DD*DD];                           // fused Wq|Wk|Wv fp16
__device__ __half g_wo16[DD*DD];                            // Wo fp16
__device__ __half g_c16[BS*DD];                             // ctx fp16

__device__ __half g_q16[BS*DD];                             // Q (scaled) fp16
__device__ __half g_k16[BS*DD];                             // K fp16
__device__ __half g_v16[BS*DD];                             // V fp16

// ---------------------------------------------------------------------------
// Portable (compute_103-safe) PTX helpers
// ---------------------------------------------------------------------------
__device__ __forceinline__ uint32_t smem_u32(const void* p) {
    uint32_t a;
    asm("{ .reg .u64 t; cvta.to.shared.u64 t, %1; cvt.u32.u64 %0, t; }" : "=r"(a) : "l"(p));
    return a;
}
__device__ __forceinline__ void cp16(uint32_t dst, const void* src) {
    asm volatile("cp.async.cg.shared.global [%0], [%1], 16;" :: "r"(dst), "l"(src) : "memory");
}
#define CP_COMMIT() asm volatile("cp.async.commit_group;" ::: "memory")
#define CP_WAIT0()  asm volatile("cp.async.wait_group 0;" ::: "memory")
#define CP_WAIT1()  asm volatile("cp.async.wait_group 1;" ::: "memory")
#define CP_WAIT2()  asm volatile("cp.async.wait_group 2;" ::: "memory")

__device__ __forceinline__ void ldsm4(uint32_t& r0, uint32_t& r1, uint32_t& r2, uint32_t& r3,
                                      uint32_t addr) {
    asm volatile("ldmatrix.sync.aligned.m8n8.x4.shared.b16 {%0,%1,%2,%3}, [%4];"
                 : "=r"(r0), "=r"(r1), "=r"(r2), "=r"(r3) : "r"(addr));
}
__device__ __forceinline__ void ldsm4t(uint32_t& r0, uint32_t& r1, uint32_t& r2, uint32_t& r3,
                                       uint32_t addr) {
    asm volatile("ldmatrix.sync.aligned.m8n8.x4.trans.shared.b16 {%0,%1,%2,%3}, [%4];"
                 : "=r"(r0), "=r"(r1), "=r"(r2), "=r"(r3) : "r"(addr));
}
// fp16 mma
__device__ __forceinline__ void mma16816h(float* c,
                                          uint32_t a0, uint32_t a1, uint32_t a2, uint32_t a3,
                                          uint32_t b0, uint32_t b1) {
    asm volatile("mma.sync.aligned.m16n8k16.row.col.f32.f16.f16.f32 "
                 "{%0,%1,%2,%3}, {%4,%5,%6,%7}, {%8,%9}, {%0,%1,%2,%3};"
                 : "+f"(c[0]), "+f"(c[1]), "+f"(c[2]), "+f"(c[3])
                 : "r"(a0), "r"(a1), "r"(a2), "r"(a3), "r"(b0), "r"(b1));
}
__device__ __forceinline__ float ex2f(float x) {
    float y; asm("ex2.approx.f32 %0, %1;" : "=f"(y) : "f"(x)); return y;
}
__device__ __forceinline__ uint32_t packh(float x, float y) {
    __half2 t = __floats2half2_rn(x, y);
    return *(uint32_t*)&t;
}

// ---------------------------------------------------------------------------
// Fused fp32 -> fp16 convert (2 independent chunks per thread for MLP)
// ---------------------------------------------------------------------------
#define XN4 (BS*DD/4)      // 2097152
#define WN4 (DD*DD/4)      // 262144
#define CVT_TOTAL (XN4 + 4*WN4)
#define CVT_HALF  (CVT_TOTAL / 2)

__device__ __forceinline__ void cvt_one(int i,
                                        const float* __restrict__ x,
                                        const float* __restrict__ wq,
                                        const float* __restrict__ wk,
                                        const float* __restrict__ wv,
                                        const float* __restrict__ wo)
{
    const float* src;
    __half* dst;
    int off;
    if (i < XN4)                { src = x;  dst = g_x16;            off = i; }
    else if (i < XN4 + WN4)     { src = wq; dst = g_w16;            off = i - XN4; }
    else if (i < XN4 + 2*WN4)   { src = wk; dst = g_w16 + DD*DD;    off = i - XN4 - WN4; }
    else if (i < XN4 + 3*WN4)   { src = wv; dst = g_w16 + 2*DD*DD;  off = i - XN4 - 2*WN4; }
    else                        { src = wo; dst = g_wo16;           off = i - XN4 - 3*WN4; }
    float4 v = ((const float4*)src)[off];
    ((uint32_t*)dst)[off*2+0] = packh(v.x, v.y);
    ((uint32_t*)dst)[off*2+1] = packh(v.z, v.w);
}

__global__ __launch_bounds__(256)
void cvt_all_kernel(const float* __restrict__ x,
                    const float* __restrict__ wq, const float* __restrict__ wk,
                    const float* __restrict__ wv, const float* __restrict__ wo)
{
    int i = blockIdx.x * 256 + threadIdx.x;
    if (i >= CVT_HALF) return;
    cvt_one(i, x, wq, wk, wv, wo);
    cvt_one(i + CVT_HALF, x, wq, wk, wv, wo);
}

// ---------------------------------------------------------------------------
// fp16 single-pass GEMM via mma.sync: C = A * B^T.
// CTA 128x128, BK=64, 3-stage cp.async, 8 warps (2M x 4N), warp 64x32.
// 2 CTAs per SM; 16 k-chunks; prefetch deferred past first kst block.
// ---------------------------------------------------------------------------
#define GM_BM 128
#define GM_BN 128
#define GM_BK 64
#define GM_TILES 16            // K=1024 / 64
#define LSTR 72                // smem row stride in halves (144B), conflict-free
#define GM_THREADS 256

#define TEN_A  18432u          // 128x64 fp16 tensor (LSTR-padded)
#define STG_B  36864u          // A + B per stage
#define GSMEM  110592          // 3 stages (2 CTAs/SM -> 221KB <= 228KB)

#define QSCALE 0.18033688011112042f   // (1/8) * log2(e)

__global__ __launch_bounds__(GM_THREADS, 2)
void gemm_fp16_kernel(const __half* __restrict__ Aa,
                      const __half* __restrict__ Bw,
                      float* __restrict__ outp,
                      const float* __restrict__ bias,
                      int mode)
{
    extern __shared__ char smem[];
    const uint32_t sb = smem_u32(smem);

    const int tid = threadIdx.x;
    const int lid = tid & 31;
    const int wid = tid >> 5;     // 0..7
    const int wm = wid >> 2;      // 0..1 (64 rows)
    const int wn = wid & 3;       // 0..3 (32 cols)

    const int m0 = blockIdx.x * GM_BM;
    const int n0 = blockIdx.y * GM_BN;

    float acc[4][4][4];
    #pragma unroll
    for (int i = 0; i < 4; i++)
        #pragma unroll
        for (int j = 0; j < 4; j++)
            #pragma unroll
            for (int c = 0; c < 4; c++) acc[i][j][c] = 0.f;

    auto load_tile = [&](int t) {
        const int k0 = t * GM_BK;
        const int st = t % 3;
        const uint32_t base = sb + (uint32_t)st * STG_B;
        #pragma unroll
        for (int it = 0; it < 4; it++) {
            int idx = tid + it * GM_THREADS;
            int r = idx >> 3, c = idx & 7;
            cp16(base + (uint32_t)(r * LSTR + c * 8) * 2,
                 Aa + (size_t)(m0 + r) * DD + k0 + c * 8);
        }
        #pragma unroll
        for (int it = 0; it < 4; it++) {
            int idx = tid + it * GM_THREADS;
            int r = idx >> 3, c = idx & 7;
            cp16(base + TEN_A + (uint32_t)(r * LSTR + c * 8) * 2,
                 Bw + (size_t)(n0 + r) * DD + k0 + c * 8);
        }
        CP_COMMIT();
    };

    load_tile(0);
    load_tile(1);

    const int q = lid >> 3;
    const int r = lid & 7;
    const int arow = r + (q & 1) * 8;
    const int acol = (q >> 1) * 8;
    const int brow = r + (q >> 1) * 8;
    const int bcol = (q & 1) * 8;

    for (int i = 0; i < GM_TILES; i++) {
        if (i + 1 < GM_TILES) { CP_WAIT1(); } else { CP_WAIT0(); }
        __syncthreads();

        const uint32_t stg = sb + (uint32_t)(i % 3) * STG_B;

        // kst = 0 first (fragments on the critical path), THEN issue prefetch
        #pragma unroll
        for (int kst = 0; kst < 4; kst++) {
            const int kb = kst * 16;
            uint32_t b[4][2];
            #pragma unroll
            for (int np = 0; np < 2; np++) {
                uint32_t addr = stg + TEN_A +
                    (uint32_t)((wn * 32 + np * 16 + brow) * LSTR + kb + bcol) * 2;
                ldsm4(b[2*np][0], b[2*np][1], b[2*np+1][0], b[2*np+1][1], addr);
            }
            uint32_t a[4][4];
            #pragma unroll
            for (int mt = 0; mt < 4; mt++) {
                uint32_t addr = stg +
                    (uint32_t)((wm * 64 + mt * 16 + arow) * LSTR + kb + acol) * 2;
                ldsm4(a[mt][0], a[mt][1], a[mt][2], a[mt][3], addr);
            }
            #pragma unroll
            for (int mt = 0; mt < 4; mt++)
                #pragma unroll
                for (int nt = 0; nt < 4; nt++)
                    mma16816h(acc[mt][nt], a[mt][0], a[mt][1], a[mt][2], a[mt][3],
                              b[nt][0], b[nt][1]);
            if (kst == 0 && i + 2 < GM_TILES) load_tile(i + 2);
        }
    }

    // Epilogue
    if (mode == 0) {
        const int sel = n0 >> 10;
        __half* __restrict__ op = (sel == 0) ? g_q16 : (sel == 1) ? g_k16 : g_v16;
        const float scale = (sel == 0) ? QSCALE : 1.0f;
        const int ncta = n0 & (DD - 1);
        #pragma unroll
        for (int mt = 0; mt < 4; mt++) {
            int row = m0 + wm * 64 + mt * 16 + (lid >> 2);
            #pragma unroll
            for (int nt = 0; nt < 4; nt++) {
                int col = ncta + wn * 32 + nt * 8 + (lid & 3) * 2;
                *(uint32_t*)&op[(size_t)row * DD + col] =
                    packh(acc[mt][nt][0] * scale, acc[mt][nt][1] * scale);
                *(uint32_t*)&op[(size_t)(row + 8) * DD + col] =
                    packh(acc[mt][nt][2] * scale, acc[mt][nt][3] * scale);
            }
        }
    } else {
        #pragma unroll
        for (int mt = 0; mt < 4; mt++) {
            int row = m0 + wm * 64 + mt * 16 + (lid >> 2);
            #pragma unroll
            for (int nt = 0; nt < 4; nt++) {
                int col = n0 + wn * 32 + nt * 8 + (lid & 3) * 2;
                float2 bb = *(const float2*)&bias[col];
                float2 v0 = {acc[mt][nt][0] + bb.x, acc[mt][nt][1] + bb.y};
                float2 v1 = {acc[mt][nt][2] + bb.x, acc[mt][nt][3] + bb.y};
                *(float2*)&outp[(size_t)row * DD + col] = v0;
                *(float2*)&outp[(size_t)(row + 8) * DD + col] = v1;
            }
        }
    }
}

// ---------------------------------------------------------------------------
// Flash attention (causal), fp16 MMA, all single-pass.
// LPT scheduling: heavy q-tiles (large itile) launch FIRST.
// 3-stage KV ring, one __syncthreads per k-tile, prefetch after S-MMA.
// ---------------------------------------------------------------------------
#define BR 128
#define BC 64
#define KSTR 72                 // padded fp16 stride (144B rows)

#define FQ_OFF  0u              // Q: 128*72*2 = 18432
#define FST_OFF 18432u          // 3 stages of 18432
#define FSTAGE  18432u          // per stage: K +0, V +9216
#define FTEN    9216u
#define FSMEM   73728

__global__ __launch_bounds__(256)
void flash_mma_kernel()
{
    extern __shared__ char smem[];
    const uint32_t sb = smem_u32(smem);

    const int tid = threadIdx.x;
    const int lid = tid & 31;
    const int wid = tid >> 5;
    const int itile = (SS / BR - 1) - blockIdx.x;   // LPT: heavy tiles first
    const int bh = blockIdx.y;
    const int b = bh >> 4, h = bh & 15;
    const int qbase = itile * BR;
    const int nkt = 2 * itile + 2;

    const size_t gq  = ((size_t)(b * SS + qbase)) * DD + h * HD;
    const size_t gkv = ((size_t)(b * SS)) * DD + h * HD;

    // Q -> smem
    #pragma unroll
    for (int t = 0; t < 4; t++) {
        int idx = tid + t * 256;            // 0..1023
        int r = idx >> 3;
        int c = idx & 7;
        cp16(sb + FQ_OFF + (uint32_t)(r * KSTR + c * 8) * 2,
             g_q16 + gq + (size_t)r * DD + c * 8);
    }
    CP_COMMIT();

    auto load_kv = [&](int kt) {
        const uint32_t base = sb + FST_OFF + (uint32_t)(kt % 3) * FSTAGE;
        const size_t gk = gkv + (size_t)(kt * BC) * DD;
        #pragma unroll
        for (int t = 0; t < 4; t++) {
            int idx = tid + t * 256;        // 0..1023
            int ten = idx >> 9;             // 0 = K, 1 = V
            int r = (idx >> 3) & 63;
            int c = idx & 7;
            const __half* src = ten ? g_v16 : g_k16;
            cp16(base + (uint32_t)ten * FTEN + (uint32_t)(r * KSTR + c * 8) * 2,
                 src + gk + (size_t)r * DD + c * 8);
        }
        CP_COMMIT();
    };

    load_kv(0);
    if (nkt > 1) load_kv(1);

    CP_WAIT2();                 // Q group done (kv0/kv1 may be pending)
    __syncthreads();

    const int q4 = lid >> 3;
    const int r8 = lid & 7;
    const int arow = r8 + (q4 & 1) * 8;
    const int acol = (q4 >> 1) * 8;
    const int brow = r8 + (q4 >> 1) * 8;
    const int bcol = (q4 & 1) * 8;

    uint32_t qf[4][4];
    #pragma unroll
    for (int ks = 0; ks < 4; ks++) {
        uint32_t ao = (uint32_t)((wid * 16 + arow) * KSTR + ks * 16 + acol) * 2;
        ldsm4(qf[ks][0], qf[ks][1], qf[ks][2], qf[ks][3], sb + FQ_OFF + ao);
    }

    float o[8][4];
    #pragma unroll
    for (int nf = 0; nf < 8; nf++)
        #pragma unroll
        for (int c = 0; c < 4; c++) o[nf][c] = 0.f;
    float m0 = -1e30f, m1 = -1e30f, ls0 = 0.f, ls1 = 0.f;

    const int rowg = qbase + wid * 16 + (lid >> 2);

    for (int kt = 0; kt < nkt; kt++) {
        if (kt + 1 < nkt) { CP_WAIT1(); } else { CP_WAIT0(); }
        __syncthreads();

        const uint32_t kb = sb + FST_OFF + (uint32_t)(kt % 3) * FSTAGE;

        // ---- S = Q K^T (single fp16 pass) ----
        float s[8][4];
        #pragma unroll
        for (int nf = 0; nf < 8; nf++)
            #pragma unroll
            for (int c = 0; c < 4; c++) s[nf][c] = 0.f;

        #pragma unroll
        for (int ks = 0; ks < 4; ks++) {
            #pragma unroll
            for (int np = 0; np < 4; np++) {
                uint32_t ao = (uint32_t)((np * 16 + brow) * KSTR + ks * 16 + bcol) * 2;
                uint32_t k0, k1, k2, k3;
                ldsm4(k0, k1, k2, k3, kb + ao);
                mma16816h(s[2*np],   qf[ks][0], qf[ks][1], qf[ks][2], qf[ks][3], k0, k1);
                mma16816h(s[2*np+1], qf[ks][0], qf[ks][1], qf[ks][2], qf[ks][3], k2, k3);
            }
        }

        // deferred prefetch: ring stage (kt+2)%3 == (kt-1)%3, consumed last iter
        if (kt + 2 < nkt) load_kv(kt + 2);

        // ---- causal mask on the last two k-tiles ----
        if (kt >= nkt - 2) {
            const int colb = kt * BC + (lid & 3) * 2;
            #pragma unroll
            for (int nf = 0; nf < 8; nf++) {
                int c0 = colb + nf * 8;
                if (c0     > rowg)     s[nf][0] = -1e30f;
                if (c0 + 1 > rowg)     s[nf][1] = -1e30f;
                if (c0     > rowg + 8) s[nf][2] = -1e30f;
                if (c0 + 1 > rowg + 8) s[nf][3] = -1e30f;
            }
        }

        // ---- online softmax (log2 domain) ----
        float mx0 = -1e30f, mx1 = -1e30f;
        #pragma unroll
        for (int nf = 0; nf < 8; nf++) {
            mx0 = fmaxf(mx0, fmaxf(s[nf][0], s[nf][1]));
            mx1 = fmaxf(mx1, fmaxf(s[nf][2], s[nf][3]));
        }
        mx0 = fmaxf(mx0, __shfl_xor_sync(0xffffffffu, mx0, 1));
        mx0 = fmaxf(mx0, __shfl_xor_sync(0xffffffffu, mx0, 2));
        mx1 = fmaxf(mx1, __shfl_xor_sync(0xffffffffu, mx1, 1));
        mx1 = fmaxf(mx1, __shfl_xor_sync(0xffffffffu, mx1, 2));
        const float nm0 = fmaxf(m0, mx0), nm1 = fmaxf(m1, mx1);
        const float al0 = ex2f(m0 - nm0), al1 = ex2f(m1 - nm1);
        m0 = nm0; m1 = nm1;
        ls0 *= al0; ls1 *= al1;

        #pragma unroll
        for (int nf = 0; nf < 8; nf++) {
            s[nf][0] = ex2f(s[nf][0] - m0);
            s[nf][1] = ex2f(s[nf][1] - m0);
            s[nf][2] = ex2f(s[nf][2] - m1);
            s[nf][3] = ex2f(s[nf][3] - m1);
            ls0 += s[nf][0] + s[nf][1];
            ls1 += s[nf][2] + s[nf][3];
        }
        #pragma unroll
        for (int nf = 0; nf < 8; nf++) {
            o[nf][0] *= al0; o[nf][1] *= al0;
            o[nf][2] *= al1; o[nf][3] *= al1;
        }

        // ---- O += P V (fp16 single pass) ----
        const int vlane_r = lid & 15;
        const int vlane_c = (lid >> 4) * 8;
        #pragma unroll
        for (int ks = 0; ks < 4; ks++) {
            uint32_t pa[4];
            pa[0] = packh(s[2*ks][0],   s[2*ks][1]);
            pa[1] = packh(s[2*ks][2],   s[2*ks][3]);
            pa[2] = packh(s[2*ks+1][0], s[2*ks+1][1]);
            pa[3] = packh(s[2*ks+1][2], s[2*ks+1][3]);
            #pragma unroll
            for (int np = 0; np < 4; np++) {
                uint32_t ao = (uint32_t)((ks * 16 + vlane_r) * KSTR + np * 16 + vlane_c) * 2;
                uint32_t v0, v1, v2, v3;
                ldsm4t(v0, v1, v2, v3, kb + FTEN + ao);
                mma16816h(o[2*np],   pa[0], pa[1], pa[2], pa[3], v0, v1);
                mma16816h(o[2*np+1], pa[0], pa[1], pa[2], pa[3], v2, v3);
            }
        }
        // no trailing barrier: 3-stage ring makes next iteration's loads safe
    }

    // ---- epilogue: normalize, write ctx fp16 ----
    ls0 += __shfl_xor_sync(0xffffffffu, ls0, 1);
    ls0 += __shfl_xor_sync(0xffffffffu, ls0, 2);
    ls1 += __shfl_xor_sync(0xffffffffu, ls1, 1);
    ls1 += __shfl_xor_sync(0xffffffffu, ls1, 2);
    const float li0 = 1.0f / ls0, li1 = 1.0f / ls1;

    const size_t row0 = (size_t)(b * SS + rowg);
    const int colb = h * HD + (lid & 3) * 2;
    #pragma unroll
    for (int nf = 0; nf < 8; nf++) {
        int col = colb + nf * 8;
        *(uint32_t*)&g_c16[row0 * DD + col]       = packh(o[nf][0] * li0, o[nf][1] * li0);
        *(uint32_t*)&g_c16[(row0 + 8) * DD + col] = packh(o[nf][2] * li1, o[nf][3] * li1);
    }
}

// ---------------------------------------------------------------------------

extern "C" void kernel_launch(void* const* d_in, const int* in_sizes, int n_in,
                              void* d_out, int out_size)
{
    const float* x    = (const float*)d_in[0];
    const float* wq   = (const float*)d_in[1];
    const float* wk   = (const float*)d_in[2];
    const float* wv   = (const float*)d_in[3];
    const float* wo   = (const float*)d_in[4];
    const float* wo_b = (const float*)d_in[5];
    float* out = (float*)d_out;

    static int attr_done = 0;
    if (!attr_done) {
        cudaFuncSetAttribute(flash_mma_kernel,
                             cudaFuncAttributeMaxDynamicSharedMemorySize, FSMEM);
        cudaFuncSetAttribute(gemm_fp16_kernel,
                             cudaFuncAttributeMaxDynamicSharedMemorySize, GSMEM);
        attr_done = 1;
    }

    __half *x16, *w16, *wo16, *c16;
    cudaGetSymbolAddress((void**)&x16,  g_x16);
    cudaGetSymbolAddress((void**)&w16,  g_w16);
    cudaGetSymbolAddress((void**)&wo16, g_wo16);
    cudaGetSymbolAddress((void**)&c16,  g_c16);

    // 1. convert x + all weights to fp16 (fused, 2 chunks/thread for MLP)
    cvt_all_kernel<<<(CVT_HALF + 255)/256, 256>>>(x, wq, wk, wv, wo);

    // 2. fused QKV projection (fp16 1-pass, BK=64, 2 CTAs/SM) -> Q/K/V fp16
    gemm_fp16_kernel<<<dim3(BS/GM_BM, 3*DD/GM_BN), GM_THREADS, GSMEM>>>(
        x16, w16, nullptr, nullptr, 0);

    // 3. causal flash attention (fp16, LPT scheduling) -> ctx fp16
    flash_mma_kernel<<<dim3(SS/BR, BB*HH), 256, FSMEM>>>();

    // 4. output projection + bias (fp16 1-pass, fp32 out)
    gemm_fp16_kernel<<<dim3(BS/GM_BM, DD/GM_BN), GM_THREADS, GSMEM>>>(
        c16, wo16, out, wo_b, 1);
}

// round 16
// speedup vs baseline: 1.0965x; 1.0226x over previous
#include <cuda_runtime.h>
#include <cuda_bf16.h>
#include <cuda_fp16.h>
#include <cstdint>

// Problem constants
#define BB 4
#define SS 2048
#define DD 1024
#define HH 16
#define HD 64
#define BS (BB*SS)          // 8192

// ---------------------------------------------------------------------------
// Scratch (device globals; no allocation allowed)
// ---------------------------------------------------------------------------
__device__ __half g_x16[BS*DD];                             // x fp16
__device__ __half g_w16[3*DD*DD];                           // fused Wq|Wk|Wv fp16
__device__ __half g_wo16[DD*DD];                            // Wo fp16
__device__ __half g_c16[BS*DD];                             // ctx fp16

__device__ __half g_q16[BS*DD];                             // Q (scaled) fp16
__device__ __half g_k16[BS*DD];                             // K fp16
__device__ __half g_v16[BS*DD];                             // V fp16

// ---------------------------------------------------------------------------
// Portable (compute_103-safe) PTX helpers
// ---------------------------------------------------------------------------
__device__ __forceinline__ uint32_t smem_u32(const void* p) {
    uint32_t a;
    asm("{ .reg .u64 t; cvta.to.shared.u64 t, %1; cvt.u32.u64 %0, t; }" : "=r"(a) : "l"(p));
    return a;
}
__device__ __forceinline__ void cp16(uint32_t dst, const void* src) {
    asm volatile("cp.async.cg.shared.global [%0], [%1], 16;" :: "r"(dst), "l"(src) : "memory");
}
#define CP_COMMIT() asm volatile("cp.async.commit_group;" ::: "memory")
#define CP_WAIT0()  asm volatile("cp.async.wait_group 0;" ::: "memory")
#define CP_WAIT1()  asm volatile("cp.async.wait_group 1;" ::: "memory")
#define CP_WAIT2()  asm volatile("cp.async.wait_group 2;" ::: "memory")

// mbarrier primitives (sm_80+, valid at compute_103)
#define MBAR_INIT(addr, cnt) \
    asm volatile("mbarrier.init.shared.b64 [%0], %1;" :: "r"(addr), "r"(cnt) : "memory")
#define MBAR_ARRIVE(addr) \
    asm volatile("mbarrier.arrive.shared.b64 _, [%0];" :: "r"(addr) : "memory")
// .noinc: arrive WITHOUT incrementing pend-count (count-256 init = 256 noinc arrives)
#define CP_MBAR_ARRIVE(addr) \
    asm volatile("cp.async.mbarrier.arrive.noinc.shared.b64 [%0];" :: "r"(addr) : "memory")
#define MBAR_WAIT(addr, par) do {                                              \
    uint32_t _m = (addr), _p = (par);                                          \
    asm volatile("{\n\t.reg .pred P1;\n\t"                                     \
        "WL_%=:\n\t"                                                           \
        "mbarrier.try_wait.parity.shared.b64 P1, [%0], %1, 0x989680;\n\t"      \
        "@P1 bra.uni WD_%=;\n\t"                                               \
        "bra.uni WL_%=;\n\t"                                                   \
        "WD_%=:\n\t}"                                                          \
        :: "r"(_m), "r"(_p) : "memory");                                       \
} while (0)

__device__ __forceinline__ void ldsm4(uint32_t& r0, uint32_t& r1, uint32_t& r2, uint32_t& r3,
                                      uint32_t addr) {
    asm volatile("ldmatrix.sync.aligned.m8n8.x4.shared.b16 {%0,%1,%2,%3}, [%4];"
                 : "=r"(r0), "=r"(r1), "=r"(r2), "=r"(r3) : "r"(addr));
}
__device__ __forceinline__ void ldsm4t(uint32_t& r0, uint32_t& r1, uint32_t& r2, uint32_t& r3,
                                       uint32_t addr) {
    asm volatile("ldmatrix.sync.aligned.m8n8.x4.trans.shared.b16 {%0,%1,%2,%3}, [%4];"
                 : "=r"(r0), "=r"(r1), "=r"(r2), "=r"(r3) : "r"(addr));
}
// fp16 mma
__device__ __forceinline__ void mma16816h(float* c,
                                          uint32_t a0, uint32_t a1, uint32_t a2, uint32_t a3,
                                          uint32_t b0, uint32_t b1) {
    asm volatile("mma.sync.aligned.m16n8k16.row.col.f32.f16.f16.f32 "
                 "{%0,%1,%2,%3}, {%4,%5,%6,%7}, {%8,%9}, {%0,%1,%2,%3};"
                 : "+f"(c[0]), "+f"(c[1]), "+f"(c[2]), "+f"(c[3])
                 : "r"(a0), "r"(a1), "r"(a2), "r"(a3), "r"(b0), "r"(b1));
}
__device__ __forceinline__ float ex2f(float x) {
    float y; asm("ex2.approx.f32 %0, %1;" : "=f"(y) : "f"(x)); return y;
}
__device__ __forceinline__ uint32_t packh(float x, float y) {
    __half2 t = __floats2half2_rn(x, y);
    return *(uint32_t*)&t;
}

// ---------------------------------------------------------------------------
// Fused fp32 -> fp16 convert (2 independent chunks per thread for MLP)
// ---------------------------------------------------------------------------
#define XN4 (BS*DD/4)      // 2097152
#define WN4 (DD*DD/4)      // 262144
#define CVT_TOTAL (XN4 + 4*WN4)
#define CVT_HALF  (CVT_TOTAL / 2)

__device__ __forceinline__ void cvt_one(int i,
                                        const float* __restrict__ x,
                                        const float* __restrict__ wq,
                                        const float* __restrict__ wk,
                                        const float* __restrict__ wv,
                                        const float* __restrict__ wo)
{
    const float* src;
    __half* dst;
    int off;
    if (i < XN4)                { src = x;  dst = g_x16;            off = i; }
    else if (i < XN4 + WN4)     { src = wq; dst = g_w16;            off = i - XN4; }
    else if (i < XN4 + 2*WN4)   { src = wk; dst = g_w16 + DD*DD;    off = i - XN4 - WN4; }
    else if (i < XN4 + 3*WN4)   { src = wv; dst = g_w16 + 2*DD*DD;  off = i - XN4 - 2*WN4; }
    else                        { src = wo; dst = g_wo16;           off = i - XN4 - 3*WN4; }
    float4 v = ((const float4*)src)[off];
    ((uint32_t*)dst)[off*2+0] = packh(v.x, v.y);
    ((uint32_t*)dst)[off*2+1] = packh(v.z, v.w);
}

__global__ __launch_bounds__(256)
void cvt_all_kernel(const float* __restrict__ x,
                    const float* __restrict__ wq, const float* __restrict__ wk,
                    const float* __restrict__ wv, const float* __restrict__ wo)
{
    int i = blockIdx.x * 256 + threadIdx.x;
    if (i >= CVT_HALF) return;
    cvt_one(i, x, wq, wk, wv, wo);
    cvt_one(i + CVT_HALF, x, wq, wk, wv, wo);
}

// ---------------------------------------------------------------------------
// fp16 single-pass GEMM via mma.sync with DECOUPLED mbarrier pipeline.
// CTA 128x128, BK=64, 3-stage ring, 8 warps (2M x 4N), warp 64x32, 2 CTAs/SM.
// Per-stage full/empty mbarriers (count 256): warps skew instead of convoying.
// full[] fed by cp.async.mbarrier.arrive.NOINC (round-15 hang = missing noinc).
// ---------------------------------------------------------------------------
#define GM_BM 128
#define GM_BN 128
#define GM_BK 64
#define GM_TILES 16            // K=1024 / 64
#define LSTR 72                // smem row stride in halves (144B), conflict-free
#define GM_THREADS 256

#define MB_OFF 0u              // 6 mbarriers (full[3], empty[3]) = 48 bytes
#define TILE_OFF 128u          // stage data starts here (aligned)
#define TEN_A  18432u          // 128x64 fp16 tensor (LSTR-padded)
#define STG_B  36864u          // A + B per stage
#define GSMEM  (128 + 3*36864) // 110720 (2 CTAs/SM -> 221.4KB <= 228KB)

#define QSCALE 0.18033688011112042f   // (1/8) * log2(e)

__global__ __launch_bounds__(GM_THREADS, 2)
void gemm_fp16_kernel(const __half* __restrict__ Aa,
                      const __half* __restrict__ Bw,
                      float* __restrict__ outp,
                      const float* __restrict__ bias,
                      int mode)
{
    extern __shared__ char smem[];
    const uint32_t sb = smem_u32(smem);

    const int tid = threadIdx.x;
    const int lid = tid & 31;
    const int wid = tid >> 5;     // 0..7
    const int wm = wid >> 2;      // 0..1 (64 rows)
    const int wn = wid & 3;       // 0..3 (32 cols)

    const int m0 = blockIdx.x * GM_BM;
    const int n0 = blockIdx.y * GM_BN;

    // mbarrier setup
    if (tid == 0) {
        #pragma unroll
        for (int s = 0; s < 3; s++) {
            MBAR_INIT(sb + MB_OFF + s * 8,      GM_THREADS);   // full[s]
            MBAR_INIT(sb + MB_OFF + 24 + s * 8, GM_THREADS);   // empty[s]
        }
    }
    __syncthreads();

    float acc[4][4][4];
    #pragma unroll
    for (int i = 0; i < 4; i++)
        #pragma unroll
        for (int j = 0; j < 4; j++)
            #pragma unroll
            for (int c = 0; c < 4; c++) acc[i][j][c] = 0.f;

    // load one tile's slice (8 cp16/thread) + noinc async-arrive on full[st]
    auto load_tile = [&](int t) {
        const int k0 = t * GM_BK;
        const int st = t % 3;
        const uint32_t base = sb + TILE_OFF + (uint32_t)st * STG_B;
        #pragma unroll
        for (int it = 0; it < 4; it++) {
            int idx = tid + it * GM_THREADS;
            int r = idx >> 3, c = idx & 7;
            cp16(base + (uint32_t)(r * LSTR + c * 8) * 2,
                 Aa + (size_t)(m0 + r) * DD + k0 + c * 8);
        }
        #pragma unroll
        for (int it = 0; it < 4; it++) {
            int idx = tid + it * GM_THREADS;
            int r = idx >> 3, c = idx & 7;
            cp16(base + TEN_A + (uint32_t)(r * LSTR + c * 8) * 2,
                 Bw + (size_t)(n0 + r) * DD + k0 + c * 8);
        }
        CP_MBAR_ARRIVE(sb + MB_OFF + st * 8);
    };

    load_tile(0);
    load_tile(1);

    const int q = lid >> 3;
    const int r = lid & 7;
    const int arow = r + (q & 1) * 8;
    const int acol = (q >> 1) * 8;
    const int brow = r + (q >> 1) * 8;
    const int bcol = (q & 1) * 8;

    for (int t = 0; t < GM_TILES; t++) {
        const int st = t % 3;
        MBAR_WAIT(sb + MB_OFF + st * 8, (t / 3) & 1);          // data ready

        const uint32_t stg = sb + TILE_OFF + (uint32_t)st * STG_B;

        #pragma unroll
        for (int kst = 0; kst < 4; kst++) {
            const int kb = kst * 16;
            uint32_t b[4][2];
            #pragma unroll
            for (int np = 0; np < 2; np++) {
                uint32_t addr = stg + TEN_A +
                    (uint32_t)((wn * 32 + np * 16 + brow) * LSTR + kb + bcol) * 2;
                ldsm4(b[2*np][0], b[2*np][1], b[2*np+1][0], b[2*np+1][1], addr);
            }
            uint32_t a[4][4];
            #pragma unroll
            for (int mt = 0; mt < 4; mt++) {
                uint32_t addr = stg +
                    (uint32_t)((wm * 64 + mt * 16 + arow) * LSTR + kb + acol) * 2;
                ldsm4(a[mt][0], a[mt][1], a[mt][2], a[mt][3], addr);
            }
            #pragma unroll
            for (int mt = 0; mt < 4; mt++)
                #pragma unroll
                for (int nt = 0; nt < 4; nt++)
                    mma16816h(acc[mt][nt], a[mt][0], a[mt][1], a[mt][2], a[mt][3],
                              b[nt][0], b[nt][1]);
            // after first kst: issue prefetch for t+2 (stage reuse gated by empty)
            if (kst == 0 && t + 2 < GM_TILES) {
                if (t >= 1) {
                    const int tp = t + 2;
                    MBAR_WAIT(sb + MB_OFF + 24 + (tp % 3) * 8, (tp / 3 - 1) & 1);
                }
                load_tile(t + 2);
            }
        }
        MBAR_ARRIVE(sb + MB_OFF + 24 + st * 8);                // done reading stage
    }

    // Epilogue
    if (mode == 0) {
        const int sel = n0 >> 10;
        __half* __restrict__ op = (sel == 0) ? g_q16 : (sel == 1) ? g_k16 : g_v16;
        const float scale = (sel == 0) ? QSCALE : 1.0f;
        const int ncta = n0 & (DD - 1);
        #pragma unroll
        for (int mt = 0; mt < 4; mt++) {
            int row = m0 + wm * 64 + mt * 16 + (lid >> 2);
            #pragma unroll
            for (int nt = 0; nt < 4; nt++) {
                int col = ncta + wn * 32 + nt * 8 + (lid & 3) * 2;
                *(uint32_t*)&op[(size_t)row * DD + col] =
                    packh(acc[mt][nt][0] * scale, acc[mt][nt][1] * scale);
                *(uint32_t*)&op[(size_t)(row + 8) * DD + col] =
                    packh(acc[mt][nt][2] * scale, acc[mt][nt][3] * scale);
            }
        }
    } else {
        #pragma unroll
        for (int mt = 0; mt < 4; mt++) {
            int row = m0 + wm * 64 + mt * 16 + (lid >> 2);
            #pragma unroll
            for (int nt = 0; nt < 4; nt++) {
                int col = n0 + wn * 32 + nt * 8 + (lid & 3) * 2;
                float2 bb = *(const float2*)&bias[col];
                float2 v0 = {acc[mt][nt][0] + bb.x, acc[mt][nt][1] + bb.y};
                float2 v1 = {acc[mt][nt][2] + bb.x, acc[mt][nt][3] + bb.y};
                *(float2*)&outp[(size_t)row * DD + col] = v0;
                *(float2*)&outp[(size_t)(row + 8) * DD + col] = v1;
            }
        }
    }
}

// ---------------------------------------------------------------------------
// Flash attention (causal), fp16 MMA, all single-pass.  (round-14 proven)
// LPT scheduling, 3-stage KV ring, one __syncthreads per k-tile.
// ---------------------------------------------------------------------------
#define BR 128
#define BC 64
#define KSTR 72                 // padded fp16 stride (144B rows)

#define FQ_OFF  0u              // Q: 128*72*2 = 18432
#define FST_OFF 18432u          // 3 stages of 18432
#define FSTAGE  18432u          // per stage: K +0, V +9216
#define FTEN    9216u
#define FSMEM   73728

__global__ __launch_bounds__(256)
void flash_mma_kernel()
{
    extern __shared__ char smem[];
    const uint32_t sb = smem_u32(smem);

    const int tid = threadIdx.x;
    const int lid = tid & 31;
    const int wid = tid >> 5;
    const int itile = (SS / BR - 1) - blockIdx.x;   // LPT: heavy tiles first
    const int bh = blockIdx.y;
    const int b = bh >> 4, h = bh & 15;
    const int qbase = itile * BR;
    const int nkt = 2 * itile + 2;

    const size_t gq  = ((size_t)(b * SS + qbase)) * DD + h * HD;
    const size_t gkv = ((size_t)(b * SS)) * DD + h * HD;

    // Q -> smem
    #pragma unroll
    for (int t = 0; t < 4; t++) {
        int idx = tid + t * 256;            // 0..1023
        int r = idx >> 3;
        int c = idx & 7;
        cp16(sb + FQ_OFF + (uint32_t)(r * KSTR + c * 8) * 2,
             g_q16 + gq + (size_t)r * DD + c * 8);
    }
    CP_COMMIT();

    auto load_kv = [&](int kt) {
        const uint32_t base = sb + FST_OFF + (uint32_t)(kt % 3) * FSTAGE;
        const size_t gk = gkv + (size_t)(kt * BC) * DD;
        #pragma unroll
        for (int t = 0; t < 4; t++) {
            int idx = tid + t * 256;        // 0..1023
            int ten = idx >> 9;             // 0 = K, 1 = V
            int r = (idx >> 3) & 63;
            int c = idx & 7;
            const __half* src = ten ? g_v16 : g_k16;
            cp16(base + (uint32_t)ten * FTEN + (uint32_t)(r * KSTR + c * 8) * 2,
                 src + gk + (size_t)r * DD + c * 8);
        }
        CP_COMMIT();
    };

    load_kv(0);
    if (nkt > 1) load_kv(1);

    CP_WAIT2();                 // Q group done (kv0/kv1 may be pending)
    __syncthreads();

    const int q4 = lid >> 3;
    const int r8 = lid & 7;
    const int arow = r8 + (q4 & 1) * 8;
    const int acol = (q4 >> 1) * 8;
    const int brow = r8 + (q4 >> 1) * 8;
    const int bcol = (q4 & 1) * 8;

    uint32_t qf[4][4];
    #pragma unroll
    for (int ks = 0; ks < 4; ks++) {
        uint32_t ao = (uint32_t)((wid * 16 + arow) * KSTR + ks * 16 + acol) * 2;
        ldsm4(qf[ks][0], qf[ks][1], qf[ks][2], qf[ks][3], sb + FQ_OFF + ao);
    }

    float o[8][4];
    #pragma unroll
    for (int nf = 0; nf < 8; nf++)
        #pragma unroll
        for (int c = 0; c < 4; c++) o[nf][c] = 0.f;
    float m0 = -1e30f, m1 = -1e30f, ls0 = 0.f, ls1 = 0.f;

    const int rowg = qbase + wid * 16 + (lid >> 2);

    for (int kt = 0; kt < nkt; kt++) {
        if (kt + 1 < nkt) { CP_WAIT1(); } else { CP_WAIT0(); }
        __syncthreads();

        const uint32_t kb = sb + FST_OFF + (uint32_t)(kt % 3) * FSTAGE;

        // ---- S = Q K^T (single fp16 pass) ----
        float s[8][4];
        #pragma unroll
        for (int nf = 0; nf < 8; nf++)
            #pragma unroll
            for (int c = 0; c < 4; c++) s[nf][c] = 0.f;

        #pragma unroll
        for (int ks = 0; ks < 4; ks++) {
            #pragma unroll
            for (int np = 0; np < 4; np++) {
                uint32_t ao = (uint32_t)((np * 16 + brow) * KSTR + ks * 16 + bcol) * 2;
                uint32_t k0, k1, k2, k3;
                ldsm4(k0, k1, k2, k3, kb + ao);
                mma16816h(s[2*np],   qf[ks][0], qf[ks][1], qf[ks][2], qf[ks][3], k0, k1);
                mma16816h(s[2*np+1], qf[ks][0], qf[ks][1], qf[ks][2], qf[ks][3], k2, k3);
            }
        }

        // deferred prefetch: ring stage (kt+2)%3 == (kt-1)%3, consumed last iter
        if (kt + 2 < nkt) load_kv(kt + 2);

        // ---- causal mask on the last two k-tiles ----
        if (kt >= nkt - 2) {
            const int colb = kt * BC + (lid & 3) * 2;
            #pragma unroll
            for (int nf = 0; nf < 8; nf++) {
                int c0 = colb + nf * 8;
                if (c0     > rowg)     s[nf][0] = -1e30f;
                if (c0 + 1 > rowg)     s[nf][1] = -1e30f;
                if (c0     > rowg + 8) s[nf][2] = -1e30f;
                if (c0 + 1 > rowg + 8) s[nf][3] = -1e30f;
            }
        }

        // ---- online softmax (log2 domain) ----
        float mx0 = -1e30f, mx1 = -1e30f;
        #pragma unroll
        for (int nf = 0; nf < 8; nf++) {
            mx0 = fmaxf(mx0, fmaxf(s[nf][0], s[nf][1]));
            mx1 = fmaxf(mx1, fmaxf(s[nf][2], s[nf][3]));
        }
        mx0 = fmaxf(mx0, __shfl_xor_sync(0xffffffffu, mx0, 1));
        mx0 = fmaxf(mx0, __shfl_xor_sync(0xffffffffu, mx0, 2));
        mx1 = fmaxf(mx1, __shfl_xor_sync(0xffffffffu, mx1, 1));
        mx1 = fmaxf(mx1, __shfl_xor_sync(0xffffffffu, mx1, 2));
        const float nm0 = fmaxf(m0, mx0), nm1 = fmaxf(m1, mx1);
        const float al0 = ex2f(m0 - nm0), al1 = ex2f(m1 - nm1);
        m0 = nm0; m1 = nm1;
        ls0 *= al0; ls1 *= al1;

        #pragma unroll
        for (int nf = 0; nf < 8; nf++) {
            s[nf][0] = ex2f(s[nf][0] - m0);
            s[nf][1] = ex2f(s[nf][1] - m0);
            s[nf][2] = ex2f(s[nf][2] - m1);
            s[nf][3] = ex2f(s[nf][3] - m1);
            ls0 += s[nf][0] + s[nf][1];
            ls1 += s[nf][2] + s[nf][3];
        }
        #pragma unroll
        for (int nf = 0; nf < 8; nf++) {
            o[nf][0] *= al0; o[nf][1] *= al0;
            o[nf][2] *= al1; o[nf][3] *= al1;
        }

        // ---- O += P V (fp16 single pass) ----
        const int vlane_r = lid & 15;
        const int vlane_c = (lid >> 4) * 8;
        #pragma unroll
        for (int ks = 0; ks < 4; ks++) {
            uint32_t pa[4];
            pa[0] = packh(s[2*ks][0],   s[2*ks][1]);
            pa[1] = packh(s[2*ks][2],   s[2*ks][3]);
            pa[2] = packh(s[2*ks+1][0], s[2*ks+1][1]);
            pa[3] = packh(s[2*ks+1][2], s[2*ks+1][3]);
            #pragma unroll
            for (int np = 0; np < 4; np++) {
                uint32_t ao = (uint32_t)((ks * 16 + vlane_r) * KSTR + np * 16 + vlane_c) * 2;
                uint32_t v0, v1, v2, v3;
                ldsm4t(v0, v1, v2, v3, kb + FTEN + ao);
                mma16816h(o[2*np],   pa[0], pa[1], pa[2], pa[3], v0, v1);
                mma16816h(o[2*np+1], pa[0], pa[1], pa[2], pa[3], v2, v3);
            }
        }
        // no trailing barrier: 3-stage ring makes next iteration's loads safe
    }

    // ---- epilogue: normalize, write ctx fp16 ----
    ls0 += __shfl_xor_sync(0xffffffffu, ls0, 1);
    ls0 += __shfl_xor_sync(0xffffffffu, ls0, 2);
    ls1 += __shfl_xor_sync(0xffffffffu, ls1, 1);
    ls1 += __shfl_xor_sync(0xffffffffu, ls1, 2);
    const float li0 = 1.0f / ls0, li1 = 1.0f / ls1;

    const size_t row0 = (size_t)(b * SS + rowg);
    const int colb = h * HD + (lid & 3) * 2;
    #pragma unroll
    for (int nf = 0; nf < 8; nf++) {
        int col = colb + nf * 8;
        *(uint32_t*)&g_c16[row0 * DD + col]       = packh(o[nf][0] * li0, o[nf][1] * li0);
        *(uint32_t*)&g_c16[(row0 + 8) * DD + col] = packh(o[nf][2] * li1, o[nf][3] * li1);
    }
}

// ---------------------------------------------------------------------------

extern "C" void kernel_launch(void* const* d_in, const int* in_sizes, int n_in,
                              void* d_out, int out_size)
{
    const float* x    = (const float*)d_in[0];
    const float* wq   = (const float*)d_in[1];
    const float* wk   = (const float*)d_in[2];
    const float* wv   = (const float*)d_in[3];
    const float* wo   = (const float*)d_in[4];
    const float* wo_b = (const float*)d_in[5];
    float* out = (float*)d_out;

    static int attr_done = 0;
    if (!attr_done) {
        cudaFuncSetAttribute(flash_mma_kernel,
                             cudaFuncAttributeMaxDynamicSharedMemorySize, FSMEM);
        cudaFuncSetAttribute(gemm_fp16_kernel,
                             cudaFuncAttributeMaxDynamicSharedMemorySize, GSMEM);
        attr_done = 1;
    }

    __half *x16, *w16, *wo16, *c16;
    cudaGetSymbolAddress((void**)&x16,  g_x16);
    cudaGetSymbolAddress((void**)&w16,  g_w16);
    cudaGetSymbolAddress((void**)&wo16, g_wo16);
    cudaGetSymbolAddress((void**)&c16,  g_c16);

    // 1. convert x + all weights to fp16 (fused, 2 chunks/thread for MLP)
    cvt_all_kernel<<<(CVT_HALF + 255)/256, 256>>>(x, wq, wk, wv, wo);

    // 2. fused QKV projection (mbarrier-decoupled pipeline) -> Q/K/V fp16
    gemm_fp16_kernel<<<dim3(BS/GM_BM, 3*DD/GM_BN), GM_THREADS, GSMEM>>>(
        x16, w16, nullptr, nullptr, 0);

    // 3. causal flash attention (fp16, LPT scheduling) -> ctx fp16
    flash_mma_kernel<<<dim3(SS/BR, BB*HH), 256, FSMEM>>>();

    // 4. output projection + bias (mbarrier-decoupled pipeline, fp32 out)
    gemm_fp16_kernel<<<dim3(BS/GM_BM, DD/GM_BN), GM_THREADS, GSMEM>>>(
        c16, wo16, out, wo_b, 1);
}